// round 14
// baseline (speedup 1.0000x reference)
#include <cuda_runtime.h>
#include <cuda_fp16.h>
#include <cstdint>

#define NN 64
#define HH 512
#define TB 128
#define NT 512     // threads per CTA (16 warps)

#define PITW  72   // pitch (halves) for [*][64k] fp16 tiles: X/A3, W1/W3 chunks
#define PIT2  136  // pitch (halves) for [64m][128k] W2 chunk
#define PITR  66   // pitch (floats) for fp32 reduction buffers

// shared memory byte offsets
#define OFF_XN    0          // 128 floats
#define OFF_EPI   512        // 512 * float4 = 8192
#define OFF_X     8704       // 128*72*2 = 18432   (X; later A3)
#define OFF_W13A  27136      // W1/W3 chunk buf A
#define OFF_W13B  45568      // buf B
#define OFF_W2A   64000      // 64*136*2 = 17408   (W2 buf A)
#define OFF_W2B   81408      // buf B
#define OFF_RED0  98816      // 128*66*4 = 33792   (fp32 partial buf 0; also out-reduce)
#define OFF_RED1  132608     // buf 1
#define SMEM_BYTES 166400

// ---------------------------------------------------------------- helpers
__device__ __forceinline__ uint32_t smem_u32(const void* p) {
    uint32_t a;
    asm("{ .reg .u64 t; cvta.to.shared.u64 t, %1; cvt.u32.u64 %0, t; }"
        : "=r"(a) : "l"(p));
    return a;
}
__device__ __forceinline__ void mma16816(float c[4],
                                         uint32_t a0, uint32_t a1, uint32_t a2, uint32_t a3,
                                         uint32_t b0, uint32_t b1) {
    asm volatile(
        "mma.sync.aligned.m16n8k16.row.col.f32.f16.f16.f32 "
        "{%0,%1,%2,%3}, {%4,%5,%6,%7}, {%8,%9}, {%0,%1,%2,%3};\n"
        : "+f"(c[0]), "+f"(c[1]), "+f"(c[2]), "+f"(c[3])
        : "r"(a0), "r"(a1), "r"(a2), "r"(a3), "r"(b0), "r"(b1));
}
__device__ __forceinline__ void ldm4(uint32_t r[4], uint32_t a) {
    asm volatile("ldmatrix.sync.aligned.m8n8.x4.shared.b16 {%0,%1,%2,%3}, [%4];"
                 : "=r"(r[0]), "=r"(r[1]), "=r"(r[2]), "=r"(r[3]) : "r"(a));
}
__device__ __forceinline__ void stm4(uint32_t a, uint32_t r0, uint32_t r1,
                                     uint32_t r2, uint32_t r3) {
    asm volatile("stmatrix.sync.aligned.m8n8.x4.shared.b16 [%0], {%1,%2,%3,%4};"
                 :: "r"(a), "r"(r0), "r"(r1), "r"(r2), "r"(r3) : "memory");
}
__device__ __forceinline__ uint32_t relu_h2(float a, float b) {
    __half2 h = __floats2half2_rn(fmaxf(a, 0.f), fmaxf(b, 0.f));
    return *(uint32_t*)&h;
}
__device__ __forceinline__ uint2 cvt4(float4 v) {
    __half2 a = __floats2half2_rn(v.x, v.y);
    __half2 b = __floats2half2_rn(v.z, v.w);
    return make_uint2(*(uint32_t*)&a, *(uint32_t*)&b);
}
__device__ __forceinline__ void hstore4(__half* p, float4 v) {
    *(uint2*)p = cvt4(v);
}

// K=64 fp16 GEMM via ldmatrix: C[32b x 32n] += A @ W^T
__device__ __forceinline__ void gemm64_lm(uint32_t aB0, uint32_t aB1,
                                          uint32_t wB0, uint32_t wB1,
                                          float acc[2][4][4]) {
    #pragma unroll
    for (int ks = 0; ks < 4; ++ks) {
        uint32_t a0[4], a1[4], b0[4], b1[4];
        ldm4(a0, aB0 + ks * 32);
        ldm4(a1, aB1 + ks * 32);
        ldm4(b0, wB0 + ks * 32);
        ldm4(b1, wB1 + ks * 32);
        mma16816(acc[0][0], a0[0], a0[1], a0[2], a0[3], b0[0], b0[1]);
        mma16816(acc[0][1], a0[0], a0[1], a0[2], a0[3], b0[2], b0[3]);
        mma16816(acc[0][2], a0[0], a0[1], a0[2], a0[3], b1[0], b1[1]);
        mma16816(acc[0][3], a0[0], a0[1], a0[2], a0[3], b1[2], b1[3]);
        mma16816(acc[1][0], a1[0], a1[1], a1[2], a1[3], b0[0], b0[1]);
        mma16816(acc[1][1], a1[0], a1[1], a1[2], a1[3], b0[2], b0[3]);
        mma16816(acc[1][2], a1[0], a1[1], a1[2], a1[3], b1[0], b1[1]);
        mma16816(acc[1][3], a1[0], a1[1], a1[2], a1[3], b1[2], b1[3]);
    }
}

// ---------------------------------------------------------------- kernel
__global__ __launch_bounds__(NT, 1)
void ctp_hmma_kernel(const float* __restrict__ x,
                     const float* __restrict__ W1,
                     const float* __restrict__ W2,
                     const float* __restrict__ W3,
                     const float* __restrict__ b3,
                     const float* __restrict__ W4,
                     const float* __restrict__ b4,
                     float* __restrict__ out)
{
    extern __shared__ char sm[];
    float*  sXn  = (float*)(sm + OFF_XN);
    float4* sEpi = (float4*)(sm + OFF_EPI);
    __half* Xt   = (__half*)(sm + OFF_X);
    __half* w13p[2] = {(__half*)(sm + OFF_W13A), (__half*)(sm + OFF_W13B)};
    __half* w2p[2]  = {(__half*)(sm + OFF_W2A),  (__half*)(sm + OFF_W2B)};
    float*  Red[2]  = {(float*)(sm + OFF_RED0), (float*)(sm + OFF_RED1)};

    const uint32_t uX  = smem_u32(sm + OFF_X);
    const uint32_t uW13[2] = {smem_u32(sm + OFF_W13A), smem_u32(sm + OFF_W13B)};
    const uint32_t uW2[2]  = {smem_u32(sm + OFF_W2A),  smem_u32(sm + OFF_W2B)};

    const int tid  = threadIdx.x;
    const int lane = tid & 31;
    const int wid  = tid >> 5;          // 0..15
    const int g    = lane >> 2;
    const int tg   = lane & 3;
    const int bq   = wid & 3;           // 32-row batch group
    const int cc   = wid >> 2;          // column quarter (0..3) = stage-2 k-slice
    const int n    = blockIdx.x;
    const int r0   = blockIdx.y * TB;

    // ldmatrix per-thread offsets
    const int arow = bq * 32 + (lane & 15);
    const int acol = (lane >> 4) * 8;
    const int brow = (lane & 7) + ((lane >> 4) << 3);
    const int bcol = ((lane >> 3) & 1) * 8;
    const uint32_t aX0 = uX + (arow * PITW + acol) * 2;
    const uint32_t aX1 = aX0 + 16 * PITW * 2;
    const uint32_t w13off0 = ((cc * 32 + brow) * PITW + bcol) * 2;
    const uint32_t w13off1 = w13off0 + 16 * PITW * 2;
    // stage-2 B base: rows (m) = nh*16 + brow, k = cc*32 + jp*16 + bcol
    const uint32_t w2base  = (brow * PIT2 + cc * 32 + bcol) * 2;
    const int srow = lane & 15;
    const int scol = (lane >> 4) * 8;

    const float* W1n = W1 + n * (HH * NN);
    const float* W2n = W2 + n * (NN * HH);
    const float* W3n = W3 + n * (HH * 128);

    // ---- prologue: X tile (col n zeroed, xn captured), chunk-0 weights, epi ----
    {
        const int row = tid >> 2;
        const int q0  = (tid & 3) * 16;
        const float* xr = x + (r0 + row) * NN + q0;
        #pragma unroll
        for (int i = 0; i < 4; ++i) {
            const int c = q0 + i * 4;
            float4 v = *(const float4*)(xr + i * 4);
            if (n >= c && n < c + 4) {
                float vv[4] = {v.x, v.y, v.z, v.w};
                sXn[row] = vv[n - c];
                vv[n - c] = 0.0f;
                v = make_float4(vv[0], vv[1], vv[2], vv[3]);
            }
            hstore4(Xt + row * PITW + c, v);
        }
    }
    #pragma unroll
    for (int i = 0; i < 4; ++i) {
        const int idx = tid + i * NT;
        const int row = idx >> 4, q = (idx & 15) * 4;
        hstore4(w13p[0] + row * PITW + q, *(const float4*)(W1n + row * NN + q));
        const int m = idx >> 5, q2 = (idx & 31) * 4;
        hstore4(w2p[0] + m * PIT2 + q2, *(const float4*)(W2n + m * HH + q2));
    }
    sEpi[tid] = make_float4(W3n[tid * 128 + 64 + n],
                            b3[n * HH + tid],
                            W4[n * HH + tid], 0.0f);
    const float b4n = b4[n];

    // D2 partial: full m-width 32b x 64m over this warp's k-slices (fp32, 64 regs)
    float acc2[2][8][4] = {};

    // ========= Stages 1+2 fused in registers, over 4 H-chunks =========
    #pragma unroll
    for (int hc = 0; hc < 4; ++hc) {
        const int cur = hc & 1, nxt = cur ^ 1;
        __syncthreads();   // chunk-(hc) weights visible; [nxt] buffers free

        // refill next weight buffers (plain stores; compiler may overlap with gemm)
        if (hc < 3) {
            const float* s1 = W1n + (hc + 1) * 128 * NN;
            #pragma unroll
            for (int i = 0; i < 4; ++i) {
                const int idx = tid + i * NT;
                *(uint2*)(w13p[nxt] + (idx >> 4) * PITW + (idx & 15) * 4) =
                    cvt4(*(const float4*)(s1 + (idx >> 4) * NN + (idx & 15) * 4));
                *(uint2*)(w2p[nxt] + (idx >> 5) * PIT2 + (idx & 31) * 4) =
                    cvt4(*(const float4*)(W2n + (idx >> 5) * HH + (hc + 1) * 128 + (idx & 31) * 4));
            }
        } else {
            #pragma unroll
            for (int i = 0; i < 4; ++i) {
                const int idx = tid + i * NT;
                *(uint2*)(w13p[0] + (idx >> 4) * PITW + (idx & 15) * 4) =
                    cvt4(*(const float4*)(W3n + (idx >> 4) * 128 + (idx & 15) * 4));
            }
        }

        // stage 1: D1 slice [32b x 32h] for this warp
        float acc1[2][4][4] = {};
        gemm64_lm(aX0, aX1, uW13[cur] + w13off0, uW13[cur] + w13off1, acc1);

        // stage 2: feed relu(acc1) as A-fragments directly from registers
        #pragma unroll
        for (int jp = 0; jp < 2; ++jp) {
            uint32_t af[2][4];
            #pragma unroll
            for (int mt = 0; mt < 2; ++mt) {
                af[mt][0] = relu_h2(acc1[mt][2 * jp][0],     acc1[mt][2 * jp][1]);
                af[mt][1] = relu_h2(acc1[mt][2 * jp][2],     acc1[mt][2 * jp][3]);
                af[mt][2] = relu_h2(acc1[mt][2 * jp + 1][0], acc1[mt][2 * jp + 1][1]);
                af[mt][3] = relu_h2(acc1[mt][2 * jp + 1][2], acc1[mt][2 * jp + 1][3]);
            }
            #pragma unroll
            for (int nh = 0; nh < 4; ++nh) {
                uint32_t b[4];
                ldm4(b, uW2[cur] + w2base + (nh * 16 * PIT2 + jp * 16) * 2);
                mma16816(acc2[0][2 * nh],     af[0][0], af[0][1], af[0][2], af[0][3], b[0], b[1]);
                mma16816(acc2[0][2 * nh + 1], af[0][0], af[0][1], af[0][2], af[0][3], b[2], b[3]);
                mma16816(acc2[1][2 * nh],     af[1][0], af[1][1], af[1][2], af[1][3], b[0], b[1]);
                mma16816(acc2[1][2 * nh + 1], af[1][0], af[1][1], af[1][2], af[1][3], b[2], b[3]);
            }
        }
    }

    // ========= cross-warp k-reduction of D2 partials (fp32) =========
    __syncthreads();
    const int p = cc >> 1;
    if (cc & 1) {                         // round A: cc 1,3 store
        float* dst = Red[p];
        #pragma unroll
        for (int mt = 0; mt < 2; ++mt)
            #pragma unroll
            for (int nn = 0; nn < 8; ++nn) {
                const int r_ = bq * 32 + mt * 16 + g;
                const int m_ = nn * 8 + tg * 2;
                *(float2*)(dst + r_ * PITR + m_)       = make_float2(acc2[mt][nn][0], acc2[mt][nn][1]);
                *(float2*)(dst + (r_ + 8) * PITR + m_) = make_float2(acc2[mt][nn][2], acc2[mt][nn][3]);
            }
    }
    __syncthreads();
    if (!(cc & 1)) {                      // cc 0,2 add partner's partial
        const float* srcp = Red[p];
        #pragma unroll
        for (int mt = 0; mt < 2; ++mt)
            #pragma unroll
            for (int nn = 0; nn < 8; ++nn) {
                const int r_ = bq * 32 + mt * 16 + g;
                const int m_ = nn * 8 + tg * 2;
                float2 v0 = *(const float2*)(srcp + r_ * PITR + m_);
                float2 v1 = *(const float2*)(srcp + (r_ + 8) * PITR + m_);
                acc2[mt][nn][0] += v0.x; acc2[mt][nn][1] += v0.y;
                acc2[mt][nn][2] += v1.x; acc2[mt][nn][3] += v1.y;
            }
    }
    if (cc == 2) {                        // round B: cc2 stores its half-sum
        float* dst = Red[1];
        #pragma unroll
        for (int mt = 0; mt < 2; ++mt)
            #pragma unroll
            for (int nn = 0; nn < 8; ++nn) {
                const int r_ = bq * 32 + mt * 16 + g;
                const int m_ = nn * 8 + tg * 2;
                *(float2*)(dst + r_ * PITR + m_)       = make_float2(acc2[mt][nn][0], acc2[mt][nn][1]);
                *(float2*)(dst + (r_ + 8) * PITR + m_) = make_float2(acc2[mt][nn][2], acc2[mt][nn][3]);
            }
    }
    __syncthreads();
    if (cc == 0) {                        // cc0 finishes sum, relu -> A3 stmatrix
        const float* srcp = Red[1];
        #pragma unroll
        for (int mt = 0; mt < 2; ++mt)
            #pragma unroll
            for (int nn = 0; nn < 8; ++nn) {
                const int r_ = bq * 32 + mt * 16 + g;
                const int m_ = nn * 8 + tg * 2;
                float2 v0 = *(const float2*)(srcp + r_ * PITR + m_);
                float2 v1 = *(const float2*)(srcp + (r_ + 8) * PITR + m_);
                acc2[mt][nn][0] += v0.x; acc2[mt][nn][1] += v0.y;
                acc2[mt][nn][2] += v1.x; acc2[mt][nn][3] += v1.y;
            }
        #pragma unroll
        for (int mt = 0; mt < 2; ++mt)
            #pragma unroll
            for (int mh = 0; mh < 4; ++mh) {
                stm4(uX + ((bq * 32 + mt * 16 + srow) * PITW + mh * 16 + scol) * 2,
                     relu_h2(acc2[mt][2 * mh][0],     acc2[mt][2 * mh][1]),
                     relu_h2(acc2[mt][2 * mh][2],     acc2[mt][2 * mh][3]),
                     relu_h2(acc2[mt][2 * mh + 1][0], acc2[mt][2 * mh + 1][1]),
                     relu_h2(acc2[mt][2 * mh + 1][2], acc2[mt][2 * mh + 1][3]));
            }
    }
    __syncthreads();   // A3 visible; w13p[0] holds W3 chunk 0 (stored in phase 3)

    // xn per accumulator row group: rows {g, 8+g, 16+g, 24+g}
    float xnv[4];
    #pragma unroll
    for (int i = 0; i < 4; ++i) xnv[i] = sXn[bq * 32 + i * 8 + g];

    // =================== Stage 3 over 4 H-chunks, fused epilogue ===================
    float rowSum[4] = {};
    #pragma unroll
    for (int hc = 0; hc < 4; ++hc) {
        const int cur = hc & 1, nxt = cur ^ 1;

        uint2 r3h[4];
        if (hc < 3) {
            const float* src = W3n + (hc + 1) * 128 * 128;
            #pragma unroll
            for (int i = 0; i < 4; ++i) {
                const int idx = tid + i * NT;
                r3h[i] = cvt4(*(const float4*)(src + (idx >> 4) * 128 + (idx & 15) * 4));
            }
        }

        float acc3[2][4][4] = {};
        gemm64_lm(aX0, aX1, uW13[cur] + w13off0, uW13[cur] + w13off1, acc3);

        // z = d3 + xn*w3col + b3 ; rowSum += relu(z)*w4
        #pragma unroll
        for (int j = 0; j < 4; ++j) {
            const int colb = hc * 128 + cc * 32 + j * 8 + tg * 2;
            const float4 e0 = sEpi[colb];
            const float4 e1 = sEpi[colb + 1];
            #pragma unroll
            for (int mt = 0; mt < 2; ++mt) {
                float z;
                z = acc3[mt][j][0] + xnv[mt * 2]     * e0.x + e0.y;   // row mt*16+g
                rowSum[mt * 2]     += fmaxf(z, 0.f) * e0.z;
                z = acc3[mt][j][1] + xnv[mt * 2]     * e1.x + e1.y;
                rowSum[mt * 2]     += fmaxf(z, 0.f) * e1.z;
                z = acc3[mt][j][2] + xnv[mt * 2 + 1] * e0.x + e0.y;   // row mt*16+8+g
                rowSum[mt * 2 + 1] += fmaxf(z, 0.f) * e0.z;
                z = acc3[mt][j][3] + xnv[mt * 2 + 1] * e1.x + e1.y;
                rowSum[mt * 2 + 1] += fmaxf(z, 0.f) * e1.z;
            }
        }

        if (hc < 3) {
            #pragma unroll
            for (int i = 0; i < 4; ++i) {
                const int idx = tid + i * NT;
                *(uint2*)(w13p[nxt] + (idx >> 4) * PITW + (idx & 15) * 4) = r3h[i];
            }
        }
        __syncthreads();   // W13[nxt] stored + this iter's readers done
    }

    // reduce over the 4 k-threads of each group, then over the 4 column quarters
    float* Pred = Red[0];   // [4][128]
    #pragma unroll
    for (int i = 0; i < 4; ++i) {
        float v = rowSum[i];
        v += __shfl_xor_sync(0xffffffffu, v, 1);
        v += __shfl_xor_sync(0xffffffffu, v, 2);
        const int rr = bq * 32 + (i & 1) * 8 + (i >> 1) * 16 + g;
        if (tg == 0) Pred[cc * 128 + rr] = v;
    }
    __syncthreads();
    if (tid < 128) {
        const float tot = Pred[tid] + Pred[128 + tid] + Pred[256 + tid] + Pred[384 + tid];
        out[(r0 + tid) * NN + n] = fmaxf(tot + b4n, 0.0f);
    }
}

extern "C" void kernel_launch(void* const* d_in, const int* in_sizes, int n_in,
                              void* d_out, int out_size)
{
    const float* x  = (const float*)d_in[0];
    const float* W1 = (const float*)d_in[1];
    const float* W2 = (const float*)d_in[2];
    const float* W3 = (const float*)d_in[3];
    const float* b3 = (const float*)d_in[4];
    const float* W4 = (const float*)d_in[5];
    const float* b4 = (const float*)d_in[6];
    float* out = (float*)d_out;

    cudaFuncSetAttribute(ctp_hmma_kernel,
                         cudaFuncAttributeMaxDynamicSharedMemorySize, SMEM_BYTES);

    dim3 grid(NN, 1024 / TB);   // (64 nodes, 8 batch tiles of 128)
    ctp_hmma_kernel<<<grid, NT, SMEM_BYTES>>>(x, W1, W2, W3, b3, W4, b4, out);
}

// round 15
// speedup vs baseline: 1.2314x; 1.2314x over previous
#include <cuda_runtime.h>
#include <cuda_fp16.h>
#include <cstdint>

#define NN 64
#define HH 512
#define TB 128
#define NT 256     // 8 warps; 2 CTAs per SM

#define PITW 72    // pitch (halves) for ALL [·][64k] fp16 tiles (144B ≡ 4 banks mod 32)

// shared memory byte offsets (per CTA; total 82432 B -> 2 CTAs/SM)
#define OFF_XN    0          // 128 floats
#define OFF_EPI   512        // 512 * float4 = 8192
#define OFF_X     8704       // 128*72*2 = 18432  (X; later A3)
#define OFF_W13A  27136      // 64*72*2 = 9216   (W1/W3 chunk buf A)
#define OFF_W13B  36352      // buf B
#define OFF_W2A   45568      // W2 chunk buf A (also reduce buf at end)
#define OFF_W2B   54784      // buf B
#define OFF_A2    64000      // 128*72*2 = 18432 (relu(H1) chunk, single buf)
#define SMEM_BYTES 82432

// ---------------------------------------------------------------- helpers
__device__ __forceinline__ uint32_t smem_u32(const void* p) {
    uint32_t a;
    asm("{ .reg .u64 t; cvta.to.shared.u64 t, %1; cvt.u32.u64 %0, t; }"
        : "=r"(a) : "l"(p));
    return a;
}
__device__ __forceinline__ void mma16816(float c[4],
                                         uint32_t a0, uint32_t a1, uint32_t a2, uint32_t a3,
                                         uint32_t b0, uint32_t b1) {
    asm volatile(
        "mma.sync.aligned.m16n8k16.row.col.f32.f16.f16.f32 "
        "{%0,%1,%2,%3}, {%4,%5,%6,%7}, {%8,%9}, {%0,%1,%2,%3};\n"
        : "+f"(c[0]), "+f"(c[1]), "+f"(c[2]), "+f"(c[3])
        : "r"(a0), "r"(a1), "r"(a2), "r"(a3), "r"(b0), "r"(b1));
}
__device__ __forceinline__ void ldm4(uint32_t r[4], uint32_t a) {
    asm volatile("ldmatrix.sync.aligned.m8n8.x4.shared.b16 {%0,%1,%2,%3}, [%4];"
                 : "=r"(r[0]), "=r"(r[1]), "=r"(r[2]), "=r"(r[3]) : "r"(a));
}
__device__ __forceinline__ void stm4(uint32_t a, uint32_t r0, uint32_t r1,
                                     uint32_t r2, uint32_t r3) {
    asm volatile("stmatrix.sync.aligned.m8n8.x4.shared.b16 [%0], {%1,%2,%3,%4};"
                 :: "r"(a), "r"(r0), "r"(r1), "r"(r2), "r"(r3) : "memory");
}
__device__ __forceinline__ uint32_t relu_h2(float a, float b) {
    __half2 h = __floats2half2_rn(fmaxf(a, 0.f), fmaxf(b, 0.f));
    return *(uint32_t*)&h;
}
__device__ __forceinline__ uint2 cvt4(float4 v) {
    __half2 a = __floats2half2_rn(v.x, v.y);
    __half2 b = __floats2half2_rn(v.z, v.w);
    return make_uint2(*(uint32_t*)&a, *(uint32_t*)&b);
}
__device__ __forceinline__ void hstore4(__half* p, float4 v) {
    *(uint2*)p = cvt4(v);
}

// K=64 fp16 GEMM via ldmatrix: C[32b x 32n] += A @ W^T  (all tiles pitch PITW)
__device__ __forceinline__ void gemm64_lm(uint32_t aB0, uint32_t aB1,
                                          uint32_t wB0, uint32_t wB1,
                                          float acc[2][4][4]) {
    #pragma unroll
    for (int ks = 0; ks < 4; ++ks) {
        uint32_t a0[4], a1[4], b0[4], b1[4];
        ldm4(a0, aB0 + ks * 32);
        ldm4(a1, aB1 + ks * 32);
        ldm4(b0, wB0 + ks * 32);
        ldm4(b1, wB1 + ks * 32);
        mma16816(acc[0][0], a0[0], a0[1], a0[2], a0[3], b0[0], b0[1]);
        mma16816(acc[0][1], a0[0], a0[1], a0[2], a0[3], b0[2], b0[3]);
        mma16816(acc[0][2], a0[0], a0[1], a0[2], a0[3], b1[0], b1[1]);
        mma16816(acc[0][3], a0[0], a0[1], a0[2], a0[3], b1[2], b1[3]);
        mma16816(acc[1][0], a1[0], a1[1], a1[2], a1[3], b0[0], b0[1]);
        mma16816(acc[1][1], a1[0], a1[1], a1[2], a1[3], b0[2], b0[3]);
        mma16816(acc[1][2], a1[0], a1[1], a1[2], a1[3], b1[0], b1[1]);
        mma16816(acc[1][3], a1[0], a1[1], a1[2], a1[3], b1[2], b1[3]);
    }
}

// ---------------------------------------------------------------- kernel
__global__ __launch_bounds__(NT, 2)
void ctp_hmma_kernel(const float* __restrict__ x,
                     const float* __restrict__ W1,
                     const float* __restrict__ W2,
                     const float* __restrict__ W3,
                     const float* __restrict__ b3,
                     const float* __restrict__ W4,
                     const float* __restrict__ b4,
                     float* __restrict__ out)
{
    extern __shared__ char sm[];
    float*  sXn  = (float*)(sm + OFF_XN);
    float4* sEpi = (float4*)(sm + OFF_EPI);
    __half* Xt   = (__half*)(sm + OFF_X);
    __half* w13p[2] = {(__half*)(sm + OFF_W13A), (__half*)(sm + OFF_W13B)};
    __half* w2p[2]  = {(__half*)(sm + OFF_W2A),  (__half*)(sm + OFF_W2B)};

    const uint32_t uX  = smem_u32(sm + OFF_X);
    const uint32_t uA2 = smem_u32(sm + OFF_A2);
    const uint32_t uW13[2] = {smem_u32(sm + OFF_W13A), smem_u32(sm + OFF_W13B)};
    const uint32_t uW2[2]  = {smem_u32(sm + OFF_W2A),  smem_u32(sm + OFF_W2B)};

    const int tid  = threadIdx.x;
    const int lane = tid & 31;
    const int wid  = tid >> 5;          // 0..7
    const int g    = lane >> 2;
    const int tg   = lane & 3;
    const int bq   = wid & 3;           // 32-row batch group
    const int cc   = wid >> 2;          // column half (0..1) within 64-wide chunk
    const int n    = blockIdx.x;
    const int r0   = blockIdx.y * TB;

    // ldmatrix per-thread offsets (all tiles pitch PITW)
    const int arow = bq * 32 + (lane & 15);
    const int acol = (lane >> 4) * 8;
    const int brow = (lane & 7) + ((lane >> 4) << 3);
    const int bcol = ((lane >> 3) & 1) * 8;
    const uint32_t aX0 = uX + (arow * PITW + acol) * 2;     // X / A3
    const uint32_t aX1 = aX0 + 16 * PITW * 2;
    const uint32_t aA0 = uA2 + (arow * PITW + acol) * 2;    // A2
    const uint32_t aA1 = aA0 + 16 * PITW * 2;
    const uint32_t wOff0 = ((cc * 32 + brow) * PITW + bcol) * 2;   // W13 / W2 B-frag
    const uint32_t wOff1 = wOff0 + 16 * PITW * 2;
    // stmatrix bases
    const int srow = lane & 15;
    const int scol = (lane >> 4) * 8;
    const uint32_t stA2 = uA2 + ((bq * 32 + srow) * PITW + cc * 32 + scol) * 2;
    const uint32_t stX  = uX  + ((bq * 32 + srow) * PITW + cc * 32 + scol) * 2;

    const float* W1n = W1 + n * (HH * NN);
    const float* W2n = W2 + n * (NN * HH);
    const float* W3n = W3 + n * (HH * 128);

    // ---- prologue: X tile (col n zeroed, xn captured), chunk-0 weights, epi ----
    {
        const int row = tid >> 1, hf = tid & 1;
        const float* xr = x + (r0 + row) * NN + hf * 32;
        #pragma unroll
        for (int i = 0; i < 8; ++i) {
            const int c = hf * 32 + i * 4;
            float4 v = *(const float4*)(xr + i * 4);
            if (n >= c && n < c + 4) {
                float vv[4] = {v.x, v.y, v.z, v.w};
                sXn[row] = vv[n - c];
                vv[n - c] = 0.0f;
                v = make_float4(vv[0], vv[1], vv[2], vv[3]);
            }
            hstore4(Xt + row * PITW + c, v);
        }
    }
    #pragma unroll
    for (int i = 0; i < 4; ++i) {
        const int idx = tid + i * NT;                  // 0..1023
        const int row = idx >> 4, q = (idx & 15) * 4;  // row 0..63, q 0..60
        hstore4(w13p[0] + row * PITW + q, *(const float4*)(W1n + row * NN + q));
        hstore4(w2p[0]  + row * PITW + q, *(const float4*)(W2n + row * HH + q));
    }
    #pragma unroll
    for (int i = 0; i < 2; ++i) {
        const int idx = tid + i * NT;
        sEpi[idx] = make_float4(W3n[idx * 128 + 64 + n],
                                b3[n * HH + idx],
                                W4[n * HH + idx], 0.0f);
    }
    const float b4n = b4[n];
    __syncthreads();

    float acc2[2][4][4] = {};   // D2 [128b x 64m] warp slice (32b x 32m), persistent

    // ========= Stages 1+2 over 8 H-chunks of 64 =========
    #pragma unroll
    for (int hc = 0; hc < 8; ++hc) {
        const int cur = hc & 1, nxt = cur ^ 1;

        // prefetch next W13 chunk (W3 chunk 0 at hc=7) + next W2 chunk into regs
        uint2 r1h[4], r2h[4];
        {
            const float* s1 = (hc < 7) ? (W1n + (hc + 1) * 64 * NN) : W3n;
            const int strd  = (hc < 7) ? NN : 128;
            #pragma unroll
            for (int i = 0; i < 4; ++i) {
                const int idx = tid + i * NT;
                r1h[i] = cvt4(*(const float4*)(s1 + (idx >> 4) * strd + (idx & 15) * 4));
            }
            if (hc < 7) {
                #pragma unroll
                for (int i = 0; i < 4; ++i) {
                    const int idx = tid + i * NT;
                    r2h[i] = cvt4(*(const float4*)(W2n + (idx >> 4) * HH + (hc + 1) * 64 + (idx & 15) * 4));
                }
            }
        }

        // stage 1: D1 chunk [128b x 64h] = X @ W1c^T (hides prefetch LDGs)
        float acc1[2][4][4] = {};
        gemm64_lm(aX0, aX1, uW13[cur] + wOff0, uW13[cur] + wOff1, acc1);

        // store prefetched W13 into the other buffer (its readers done 2 bars ago)
        #pragma unroll
        for (int i = 0; i < 4; ++i) {
            const int idx = tid + i * NT;
            *(uint2*)(w13p[nxt] + (idx >> 4) * PITW + (idx & 15) * 4) = r1h[i];
        }
        __syncthreads();   // (a) gemm2(hc-1) done -> A2 free; W13[nxt] stored

        // relu + stmatrix A2(hc)
        #pragma unroll
        for (int mt = 0; mt < 2; ++mt) {
            #pragma unroll
            for (int ch = 0; ch < 2; ++ch) {
                stm4(stA2 + mt * 16 * PITW * 2 + ch * 32,
                     relu_h2(acc1[mt][2 * ch][0],     acc1[mt][2 * ch][1]),
                     relu_h2(acc1[mt][2 * ch][2],     acc1[mt][2 * ch][3]),
                     relu_h2(acc1[mt][2 * ch + 1][0], acc1[mt][2 * ch + 1][1]),
                     relu_h2(acc1[mt][2 * ch + 1][2], acc1[mt][2 * ch + 1][3]));
            }
        }
        // store prefetched W2 into the other buffer (readers finished before bar a)
        if (hc < 7) {
            #pragma unroll
            for (int i = 0; i < 4; ++i) {
                const int idx = tid + i * NT;
                *(uint2*)(w2p[nxt] + (idx >> 4) * PITW + (idx & 15) * 4) = r2h[i];
            }
        }
        __syncthreads();   // (b) A2 visible

        // stage 2 partial: D2 += A2(hc) @ W2(hc)^T  (K=64, same tile shape)
        gemm64_lm(aA0, aA1, uW2[cur] + wOff0, uW2[cur] + wOff1, acc2);
    }

    // ---- A3 = relu(D2) -> fp16 into X buffer via stmatrix ----
    // (Xt readers done since phase-7 bar(a); gemm2 doesn't touch Xt)
    #pragma unroll
    for (int mt = 0; mt < 2; ++mt) {
        #pragma unroll
        for (int ch = 0; ch < 2; ++ch) {
            stm4(stX + mt * 16 * PITW * 2 + ch * 32,
                 relu_h2(acc2[mt][2 * ch][0],     acc2[mt][2 * ch][1]),
                 relu_h2(acc2[mt][2 * ch][2],     acc2[mt][2 * ch][3]),
                 relu_h2(acc2[mt][2 * ch + 1][0], acc2[mt][2 * ch + 1][1]),
                 relu_h2(acc2[mt][2 * ch + 1][2], acc2[mt][2 * ch + 1][3]));
        }
    }
    __syncthreads();   // A3 visible; w13p[0] holds W3 chunk 0 (stored in phase 7)

    // xn per accumulator row group: rows {g, 8+g, 16+g, 24+g}
    float xnv[4];
    #pragma unroll
    for (int i = 0; i < 4; ++i) xnv[i] = sXn[bq * 32 + i * 8 + g];

    // =================== Stage 3 over 8 H-chunks of 64, fused epilogue ===================
    float rowSum[4] = {};
    #pragma unroll
    for (int hc = 0; hc < 8; ++hc) {
        const int cur = hc & 1, nxt = cur ^ 1;

        uint2 r3h[4];
        if (hc < 7) {
            const float* src = W3n + (hc + 1) * 64 * 128;
            #pragma unroll
            for (int i = 0; i < 4; ++i) {
                const int idx = tid + i * NT;
                r3h[i] = cvt4(*(const float4*)(src + (idx >> 4) * 128 + (idx & 15) * 4));
            }
        }

        float acc3[2][4][4] = {};
        gemm64_lm(aX0, aX1, uW13[cur] + wOff0, uW13[cur] + wOff1, acc3);

        // z = d3 + xn*w3col + b3 ; rowSum += relu(z)*w4
        #pragma unroll
        for (int j = 0; j < 4; ++j) {
            const int colb = hc * 64 + cc * 32 + j * 8 + tg * 2;
            const float4 e0 = sEpi[colb];
            const float4 e1 = sEpi[colb + 1];
            #pragma unroll
            for (int mt = 0; mt < 2; ++mt) {
                float z;
                z = acc3[mt][j][0] + xnv[mt * 2]     * e0.x + e0.y;   // row mt*16+g
                rowSum[mt * 2]     += fmaxf(z, 0.f) * e0.z;
                z = acc3[mt][j][1] + xnv[mt * 2]     * e1.x + e1.y;
                rowSum[mt * 2]     += fmaxf(z, 0.f) * e1.z;
                z = acc3[mt][j][2] + xnv[mt * 2 + 1] * e0.x + e0.y;   // row mt*16+8+g
                rowSum[mt * 2 + 1] += fmaxf(z, 0.f) * e0.z;
                z = acc3[mt][j][3] + xnv[mt * 2 + 1] * e1.x + e1.y;
                rowSum[mt * 2 + 1] += fmaxf(z, 0.f) * e1.z;
            }
        }

        if (hc < 7) {
            #pragma unroll
            for (int i = 0; i < 4; ++i) {
                const int idx = tid + i * NT;
                *(uint2*)(w13p[nxt] + (idx >> 4) * PITW + (idx & 15) * 4) = r3h[i];
            }
        }
        __syncthreads();   // W13[nxt] stored + this chunk's readers done
    }

    // reduce over the 4 k-threads of each group, then over the 2 column halves
    float* Pred = (float*)(sm + OFF_W2A);   // [2][128]
    #pragma unroll
    for (int i = 0; i < 4; ++i) {
        float v = rowSum[i];
        v += __shfl_xor_sync(0xffffffffu, v, 1);
        v += __shfl_xor_sync(0xffffffffu, v, 2);
        const int rr = bq * 32 + (i & 1) * 8 + (i >> 1) * 16 + g;
        if (tg == 0) Pred[cc * 128 + rr] = v;
    }
    __syncthreads();
    if (tid < 128) {
        const float tot = Pred[tid] + Pred[128 + tid];
        out[(r0 + tid) * NN + n] = fmaxf(tot + b4n, 0.0f);
    }
}

extern "C" void kernel_launch(void* const* d_in, const int* in_sizes, int n_in,
                              void* d_out, int out_size)
{
    const float* x  = (const float*)d_in[0];
    const float* W1 = (const float*)d_in[1];
    const float* W2 = (const float*)d_in[2];
    const float* W3 = (const float*)d_in[3];
    const float* b3 = (const float*)d_in[4];
    const float* W4 = (const float*)d_in[5];
    const float* b4 = (const float*)d_in[6];
    float* out = (float*)d_out;

    cudaFuncSetAttribute(ctp_hmma_kernel,
                         cudaFuncAttributeMaxDynamicSharedMemorySize, SMEM_BYTES);

    dim3 grid(NN, 1024 / TB);   // (64 nodes, 8 batch tiles of 128) = 512 CTAs
    ctp_hmma_kernel<<<grid, NT, SMEM_BYTES>>>(x, W1, W2, W3, b3, W4, b4, out);
}

// round 16
// speedup vs baseline: 1.3200x; 1.0720x over previous
#include <cuda_runtime.h>
#include <cuda_fp16.h>
#include <cstdint>

#define NN 64
#define HH 512
#define TB 128
#define NT 256     // 8 warps; 2 CTAs per SM

#define PITW 72    // pitch (halves) for ALL [·][64k] fp16 tiles (144B ≡ 4 banks mod 32)

// shared memory byte offsets (per CTA; total 82432 B -> 2 CTAs/SM)
#define OFF_XN    0          // 128 floats
#define OFF_EPI   512        // 512 * float4 = 8192
#define OFF_X     8704       // 128*72*2 = 18432  (X; later A3)
#define OFF_W13A  27136      // 64*72*2 = 9216   (W1/W3 chunk buf A)
#define OFF_W13B  36352      // buf B
#define OFF_W2A   45568      // W2 chunk buf A (also reduce buf at end)
#define OFF_W2B   54784      // buf B
#define OFF_A2    64000      // 128*72*2 = 18432 (relu(H1) chunk, single buf)
#define SMEM_BYTES 82432

// ---------------------------------------------------------------- helpers
__device__ __forceinline__ uint32_t smem_u32(const void* p) {
    uint32_t a;
    asm("{ .reg .u64 t; cvta.to.shared.u64 t, %1; cvt.u32.u64 %0, t; }"
        : "=r"(a) : "l"(p));
    return a;
}
__device__ __forceinline__ void mma16816(float c[4],
                                         uint32_t a0, uint32_t a1, uint32_t a2, uint32_t a3,
                                         uint32_t b0, uint32_t b1) {
    asm volatile(
        "mma.sync.aligned.m16n8k16.row.col.f32.f16.f16.f32 "
        "{%0,%1,%2,%3}, {%4,%5,%6,%7}, {%8,%9}, {%0,%1,%2,%3};\n"
        : "+f"(c[0]), "+f"(c[1]), "+f"(c[2]), "+f"(c[3])
        : "r"(a0), "r"(a1), "r"(a2), "r"(a3), "r"(b0), "r"(b1));
}
__device__ __forceinline__ void ldm4(uint32_t r[4], uint32_t a) {
    asm volatile("ldmatrix.sync.aligned.m8n8.x4.shared.b16 {%0,%1,%2,%3}, [%4];"
                 : "=r"(r[0]), "=r"(r[1]), "=r"(r[2]), "=r"(r[3]) : "r"(a));
}
__device__ __forceinline__ void stm4(uint32_t a, uint32_t r0, uint32_t r1,
                                     uint32_t r2, uint32_t r3) {
    asm volatile("stmatrix.sync.aligned.m8n8.x4.shared.b16 [%0], {%1,%2,%3,%4};"
                 :: "r"(a), "r"(r0), "r"(r1), "r"(r2), "r"(r3) : "memory");
}
__device__ __forceinline__ uint32_t relu_h2(float a, float b) {
    __half2 h = __floats2half2_rn(fmaxf(a, 0.f), fmaxf(b, 0.f));
    return *(uint32_t*)&h;
}
__device__ __forceinline__ uint2 cvt4(float4 v) {
    __half2 a = __floats2half2_rn(v.x, v.y);
    __half2 b = __floats2half2_rn(v.z, v.w);
    return make_uint2(*(uint32_t*)&a, *(uint32_t*)&b);
}
__device__ __forceinline__ void hstore4(__half* p, float4 v) {
    *(uint2*)p = cvt4(v);
}

// K=64 GEMM with A already in registers (xf[mt][ks][4]); B from smem.
__device__ __forceinline__ void gemm64_ra(const uint32_t xf[2][4][4],
                                          uint32_t wB0, uint32_t wB1,
                                          float acc[2][4][4]) {
    #pragma unroll
    for (int ks = 0; ks < 4; ++ks) {
        uint32_t b0[4], b1[4];
        ldm4(b0, wB0 + ks * 32);
        ldm4(b1, wB1 + ks * 32);
        mma16816(acc[0][0], xf[0][ks][0], xf[0][ks][1], xf[0][ks][2], xf[0][ks][3], b0[0], b0[1]);
        mma16816(acc[0][1], xf[0][ks][0], xf[0][ks][1], xf[0][ks][2], xf[0][ks][3], b0[2], b0[3]);
        mma16816(acc[0][2], xf[0][ks][0], xf[0][ks][1], xf[0][ks][2], xf[0][ks][3], b1[0], b1[1]);
        mma16816(acc[0][3], xf[0][ks][0], xf[0][ks][1], xf[0][ks][2], xf[0][ks][3], b1[2], b1[3]);
        mma16816(acc[1][0], xf[1][ks][0], xf[1][ks][1], xf[1][ks][2], xf[1][ks][3], b0[0], b0[1]);
        mma16816(acc[1][1], xf[1][ks][0], xf[1][ks][1], xf[1][ks][2], xf[1][ks][3], b0[2], b0[3]);
        mma16816(acc[1][2], xf[1][ks][0], xf[1][ks][1], xf[1][ks][2], xf[1][ks][3], b1[0], b1[1]);
        mma16816(acc[1][3], xf[1][ks][0], xf[1][ks][1], xf[1][ks][2], xf[1][ks][3], b1[2], b1[3]);
    }
}
// K=64 GEMM, both operands from smem (stage 2: A2 changes per chunk)
__device__ __forceinline__ void gemm64_lm(uint32_t aB0, uint32_t aB1,
                                          uint32_t wB0, uint32_t wB1,
                                          float acc[2][4][4]) {
    #pragma unroll
    for (int ks = 0; ks < 4; ++ks) {
        uint32_t a0[4], a1[4], b0[4], b1[4];
        ldm4(a0, aB0 + ks * 32);
        ldm4(a1, aB1 + ks * 32);
        ldm4(b0, wB0 + ks * 32);
        ldm4(b1, wB1 + ks * 32);
        mma16816(acc[0][0], a0[0], a0[1], a0[2], a0[3], b0[0], b0[1]);
        mma16816(acc[0][1], a0[0], a0[1], a0[2], a0[3], b0[2], b0[3]);
        mma16816(acc[0][2], a0[0], a0[1], a0[2], a0[3], b1[0], b1[1]);
        mma16816(acc[0][3], a0[0], a0[1], a0[2], a0[3], b1[2], b1[3]);
        mma16816(acc[1][0], a1[0], a1[1], a1[2], a1[3], b0[0], b0[1]);
        mma16816(acc[1][1], a1[0], a1[1], a1[2], a1[3], b0[2], b0[3]);
        mma16816(acc[1][2], a1[0], a1[1], a1[2], a1[3], b1[0], b1[1]);
        mma16816(acc[1][3], a1[0], a1[1], a1[2], a1[3], b1[2], b1[3]);
    }
}

// ---------------------------------------------------------------- kernel
__global__ __launch_bounds__(NT, 2)
void ctp_hmma_kernel(const float* __restrict__ x,
                     const float* __restrict__ W1,
                     const float* __restrict__ W2,
                     const float* __restrict__ W3,
                     const float* __restrict__ b3,
                     const float* __restrict__ W4,
                     const float* __restrict__ b4,
                     float* __restrict__ out)
{
    extern __shared__ char sm[];
    float*  sXn  = (float*)(sm + OFF_XN);
    float4* sEpi = (float4*)(sm + OFF_EPI);
    __half* Xt   = (__half*)(sm + OFF_X);
    __half* w13p[2] = {(__half*)(sm + OFF_W13A), (__half*)(sm + OFF_W13B)};
    __half* w2p[2]  = {(__half*)(sm + OFF_W2A),  (__half*)(sm + OFF_W2B)};

    const uint32_t uX  = smem_u32(sm + OFF_X);
    const uint32_t uA2 = smem_u32(sm + OFF_A2);
    const uint32_t uW13[2] = {smem_u32(sm + OFF_W13A), smem_u32(sm + OFF_W13B)};
    const uint32_t uW2[2]  = {smem_u32(sm + OFF_W2A),  smem_u32(sm + OFF_W2B)};

    const int tid  = threadIdx.x;
    const int lane = tid & 31;
    const int wid  = tid >> 5;          // 0..7
    const int g    = lane >> 2;
    const int tg   = lane & 3;
    const int bq   = wid & 3;           // 32-row batch group
    const int cc   = wid >> 2;          // column half (0..1) within 64-wide chunk
    const int n    = blockIdx.x;
    const int r0   = blockIdx.y * TB;

    // ldmatrix per-thread offsets (all tiles pitch PITW)
    const int arow = bq * 32 + (lane & 15);
    const int acol = (lane >> 4) * 8;
    const int brow = (lane & 7) + ((lane >> 4) << 3);
    const int bcol = ((lane >> 3) & 1) * 8;
    const uint32_t aX0 = uX + (arow * PITW + acol) * 2;     // X / A3
    const uint32_t aX1 = aX0 + 16 * PITW * 2;
    const uint32_t aA0 = uA2 + (arow * PITW + acol) * 2;    // A2
    const uint32_t aA1 = aA0 + 16 * PITW * 2;
    const uint32_t wOff0 = ((cc * 32 + brow) * PITW + bcol) * 2;   // W13 / W2 B-frag
    const uint32_t wOff1 = wOff0 + 16 * PITW * 2;
    // stmatrix bases
    const int srow = lane & 15;
    const int scol = (lane >> 4) * 8;
    const uint32_t stA2 = uA2 + ((bq * 32 + srow) * PITW + cc * 32 + scol) * 2;
    const uint32_t stX  = uX  + ((bq * 32 + srow) * PITW + cc * 32 + scol) * 2;

    const float* W1n = W1 + n * (HH * NN);
    const float* W2n = W2 + n * (NN * HH);
    const float* W3n = W3 + n * (HH * 128);

    // ---- prologue: X tile (col n zeroed, xn captured), chunk-0 weights, epi ----
    {
        const int row = tid >> 1, hf = tid & 1;
        const float* xr = x + (r0 + row) * NN + hf * 32;
        #pragma unroll
        for (int i = 0; i < 8; ++i) {
            const int c = hf * 32 + i * 4;
            float4 v = *(const float4*)(xr + i * 4);
            if (n >= c && n < c + 4) {
                float vv[4] = {v.x, v.y, v.z, v.w};
                sXn[row] = vv[n - c];
                vv[n - c] = 0.0f;
                v = make_float4(vv[0], vv[1], vv[2], vv[3]);
            }
            hstore4(Xt + row * PITW + c, v);
        }
    }
    #pragma unroll
    for (int i = 0; i < 4; ++i) {
        const int idx = tid + i * NT;
        const int row = idx >> 4, q = (idx & 15) * 4;
        hstore4(w13p[0] + row * PITW + q, *(const float4*)(W1n + row * NN + q));
        hstore4(w2p[0]  + row * PITW + q, *(const float4*)(W2n + row * HH + q));
    }
    #pragma unroll
    for (int i = 0; i < 2; ++i) {
        const int idx = tid + i * NT;
        sEpi[idx] = make_float4(W3n[idx * 128 + 64 + n],
                                b3[n * HH + idx],
                                W4[n * HH + idx], 0.0f);
    }
    const float b4n = b4[n];
    __syncthreads();

    // X A-fragments: loaded ONCE, reused for all 8 stage-1 chunks (Xt then dead)
    uint32_t xf[2][4][4];
    #pragma unroll
    for (int ks = 0; ks < 4; ++ks) {
        ldm4(xf[0][ks], aX0 + ks * 32);
        ldm4(xf[1][ks], aX1 + ks * 32);
    }

    float acc2[2][4][4] = {};   // D2 [128b x 64m] warp slice (32b x 32m), persistent

    // ========= Stages 1+2 over 8 H-chunks of 64 =========
    #pragma unroll
    for (int hc = 0; hc < 8; ++hc) {
        const int cur = hc & 1, nxt = cur ^ 1;

        // prefetch next W13 chunk (W3 chunk 0 at hc=7) + next W2 chunk into regs
        uint2 r1h[4], r2h[4];
        {
            const float* s1 = (hc < 7) ? (W1n + (hc + 1) * 64 * NN) : W3n;
            const int strd  = (hc < 7) ? NN : 128;
            #pragma unroll
            for (int i = 0; i < 4; ++i) {
                const int idx = tid + i * NT;
                r1h[i] = cvt4(*(const float4*)(s1 + (idx >> 4) * strd + (idx & 15) * 4));
            }
            if (hc < 7) {
                #pragma unroll
                for (int i = 0; i < 4; ++i) {
                    const int idx = tid + i * NT;
                    r2h[i] = cvt4(*(const float4*)(W2n + (idx >> 4) * HH + (hc + 1) * 64 + (idx & 15) * 4));
                }
            }
        }

        // stage 1: D1 chunk [128b x 64h] = X @ W1c^T  (A from registers)
        float acc1[2][4][4] = {};
        gemm64_ra(xf, uW13[cur] + wOff0, uW13[cur] + wOff1, acc1);

        // store prefetched W13 into the other buffer
        #pragma unroll
        for (int i = 0; i < 4; ++i) {
            const int idx = tid + i * NT;
            *(uint2*)(w13p[nxt] + (idx >> 4) * PITW + (idx & 15) * 4) = r1h[i];
        }
        __syncthreads();   // (a) gemm2(hc-1) done -> A2 free; W13[nxt] stored

        // relu + stmatrix A2(hc)
        #pragma unroll
        for (int mt = 0; mt < 2; ++mt) {
            #pragma unroll
            for (int ch = 0; ch < 2; ++ch) {
                stm4(stA2 + mt * 16 * PITW * 2 + ch * 32,
                     relu_h2(acc1[mt][2 * ch][0],     acc1[mt][2 * ch][1]),
                     relu_h2(acc1[mt][2 * ch][2],     acc1[mt][2 * ch][3]),
                     relu_h2(acc1[mt][2 * ch + 1][0], acc1[mt][2 * ch + 1][1]),
                     relu_h2(acc1[mt][2 * ch + 1][2], acc1[mt][2 * ch + 1][3]));
            }
        }
        // store prefetched W2 into the other buffer
        if (hc < 7) {
            #pragma unroll
            for (int i = 0; i < 4; ++i) {
                const int idx = tid + i * NT;
                *(uint2*)(w2p[nxt] + (idx >> 4) * PITW + (idx & 15) * 4) = r2h[i];
            }
        }
        __syncthreads();   // (b) A2 visible

        // stage 2 partial: D2 += A2(hc) @ W2(hc)^T
        gemm64_lm(aA0, aA1, uW2[cur] + wOff0, uW2[cur] + wOff1, acc2);
    }

    // ---- A3 = relu(D2) -> fp16 into X buffer via stmatrix ----
    #pragma unroll
    for (int mt = 0; mt < 2; ++mt) {
        #pragma unroll
        for (int ch = 0; ch < 2; ++ch) {
            stm4(stX + mt * 16 * PITW * 2 + ch * 32,
                 relu_h2(acc2[mt][2 * ch][0],     acc2[mt][2 * ch][1]),
                 relu_h2(acc2[mt][2 * ch][2],     acc2[mt][2 * ch][3]),
                 relu_h2(acc2[mt][2 * ch + 1][0], acc2[mt][2 * ch + 1][1]),
                 relu_h2(acc2[mt][2 * ch + 1][2], acc2[mt][2 * ch + 1][3]));
        }
    }
    __syncthreads();   // A3 visible; w13p[0] holds W3 chunk 0 (stored in phase 7)

    // A3 fragments: loaded ONCE, reused for all 8 stage-3 chunks
    #pragma unroll
    for (int ks = 0; ks < 4; ++ks) {
        ldm4(xf[0][ks], aX0 + ks * 32);
        ldm4(xf[1][ks], aX1 + ks * 32);
    }

    // xn per accumulator row group: rows {g, 8+g, 16+g, 24+g}
    float xnv[4];
    #pragma unroll
    for (int i = 0; i < 4; ++i) xnv[i] = sXn[bq * 32 + i * 8 + g];

    // =================== Stage 3 over 8 H-chunks of 64, fused epilogue ===================
    float rowSum[4] = {};
    #pragma unroll
    for (int hc = 0; hc < 8; ++hc) {
        const int cur = hc & 1, nxt = cur ^ 1;

        uint2 r3h[4];
        if (hc < 7) {
            const float* src = W3n + (hc + 1) * 64 * 128;
            #pragma unroll
            for (int i = 0; i < 4; ++i) {
                const int idx = tid + i * NT;
                r3h[i] = cvt4(*(const float4*)(src + (idx >> 4) * 128 + (idx & 15) * 4));
            }
        }

        float acc3[2][4][4] = {};
        gemm64_ra(xf, uW13[cur] + wOff0, uW13[cur] + wOff1, acc3);

        // z = d3 + xn*w3col + b3 ; rowSum += relu(z)*w4
        #pragma unroll
        for (int j = 0; j < 4; ++j) {
            const int colb = hc * 64 + cc * 32 + j * 8 + tg * 2;
            const float4 e0 = sEpi[colb];
            const float4 e1 = sEpi[colb + 1];
            #pragma unroll
            for (int mt = 0; mt < 2; ++mt) {
                float z;
                z = acc3[mt][j][0] + xnv[mt * 2]     * e0.x + e0.y;   // row mt*16+g
                rowSum[mt * 2]     += fmaxf(z, 0.f) * e0.z;
                z = acc3[mt][j][1] + xnv[mt * 2]     * e1.x + e1.y;
                rowSum[mt * 2]     += fmaxf(z, 0.f) * e1.z;
                z = acc3[mt][j][2] + xnv[mt * 2 + 1] * e0.x + e0.y;   // row mt*16+8+g
                rowSum[mt * 2 + 1] += fmaxf(z, 0.f) * e0.z;
                z = acc3[mt][j][3] + xnv[mt * 2 + 1] * e1.x + e1.y;
                rowSum[mt * 2 + 1] += fmaxf(z, 0.f) * e1.z;
            }
        }

        if (hc < 7) {
            #pragma unroll
            for (int i = 0; i < 4; ++i) {
                const int idx = tid + i * NT;
                *(uint2*)(w13p[nxt] + (idx >> 4) * PITW + (idx & 15) * 4) = r3h[i];
            }
        }
        __syncthreads();   // W13[nxt] stored + this chunk's readers done
    }

    // reduce over the 4 k-threads of each group, then over the 2 column halves
    float* Pred = (float*)(sm + OFF_W2A);   // [2][128]
    #pragma unroll
    for (int i = 0; i < 4; ++i) {
        float v = rowSum[i];
        v += __shfl_xor_sync(0xffffffffu, v, 1);
        v += __shfl_xor_sync(0xffffffffu, v, 2);
        const int rr = bq * 32 + (i & 1) * 8 + (i >> 1) * 16 + g;
        if (tg == 0) Pred[cc * 128 + rr] = v;
    }
    __syncthreads();
    if (tid < 128) {
        const float tot = Pred[tid] + Pred[128 + tid];
        out[(r0 + tid) * NN + n] = fmaxf(tot + b4n, 0.0f);
    }
}

extern "C" void kernel_launch(void* const* d_in, const int* in_sizes, int n_in,
                              void* d_out, int out_size)
{
    const float* x  = (const float*)d_in[0];
    const float* W1 = (const float*)d_in[1];
    const float* W2 = (const float*)d_in[2];
    const float* W3 = (const float*)d_in[3];
    const float* b3 = (const float*)d_in[4];
    const float* W4 = (const float*)d_in[5];
    const float* b4 = (const float*)d_in[6];
    float* out = (float*)d_out;

    cudaFuncSetAttribute(ctp_hmma_kernel,
                         cudaFuncAttributeMaxDynamicSharedMemorySize, SMEM_BYTES);

    dim3 grid(NN, 1024 / TB);   // (64 nodes, 8 batch tiles of 128) = 512 CTAs
    ctp_hmma_kernel<<<grid, NT, SMEM_BYTES>>>(x, W1, W2, W3, b3, W4, b4, out);
}